// round 1
// baseline (speedup 1.0000x reference)
#include <cuda_runtime.h>
#include <math.h>

// ============================================================================
// EcosystemTransformer — fp32 baseline
//   B=4, N=1024, D=512, H=8, L=6, DFF=2048, DH=64
// Pipeline per layer:
//   ln1 -> Q/K/V GEMMs -> S = QK^T*0.125 + bias -> softmax -> O = P V
//   -> x += O Wo + bo -> ln2 -> ff = gelu(h W1 + b1) -> x += ff W2 + b2
// Final layernorm -> out.
// ============================================================================

namespace {
constexpr int Bv   = 4;
constexpr int Nv   = 1024;
constexpr int Dv   = 512;
constexpr int Hv   = 8;
constexpr int Lv   = 6;
constexpr int DFFv = 2048;
constexpr int DHv  = 64;
constexpr int ROWS = Bv * Nv;           // 4096
constexpr float NEGINF = -1000000000.0f;
constexpr float R2 = 100.0f;
}

// Scratch buffers (static __device__ globals: allocation-guard safe)
__device__ float g_x [ROWS * Dv];
__device__ float g_h [ROWS * Dv];
__device__ float g_q [ROWS * Dv];
__device__ float g_k [ROWS * Dv];
__device__ float g_v [ROWS * Dv];
__device__ float g_o [ROWS * Dv];
__device__ float g_ff[ROWS * DFFv];
__device__ float g_S [(size_t)Bv * Hv * Nv * Nv];   // 128 MB scores/probs
__device__ float g_bias[(size_t)Bv * Nv * Nv];      // 16 MB additive bias

// Buffer selector (avoids host-side symbol address lookups)
__device__ __forceinline__ float* selbuf(int s) {
    switch (s) {
        case 0: return g_h;
        case 1: return g_o;
        case 2: return g_ff;
        case 3: return g_q;
        case 4: return g_k;
        case 5: return g_v;
        default: return g_x;
    }
}

// ----------------------------------------------------------------------------
// tokens -> g_x
// ----------------------------------------------------------------------------
__global__ void __launch_bounds__(256)
copy_tokens(const float4* __restrict__ tokens) {
    int i = blockIdx.x * 256 + threadIdx.x;   // ROWS*Dv/4 = 524288 elements
    ((float4*)g_x)[i] = tokens[i];
}

// ----------------------------------------------------------------------------
// Additive attention bias (B,N,N): dead-key + locality + species-cross masks
// ----------------------------------------------------------------------------
__global__ void __launch_bounds__(256)
build_bias(const float* __restrict__ xy,
           const int*   __restrict__ alive,
           const int*   __restrict__ species) {
    int i = blockIdx.x;        // query index
    int b = blockIdx.y;        // batch
    float xi = xy[(b * Nv + i) * 2 + 0];
    float yi = xy[(b * Nv + i) * 2 + 1];
    int   si = species[b * Nv + i];
    bool ia_i = (si < 2), ip_i = (si == 2);
    float* brow = g_bias + ((size_t)b * Nv + i) * Nv;
    for (int j = threadIdx.x; j < Nv; j += 256) {
        float dx = xi - xy[(b * Nv + j) * 2 + 0];
        float dy = yi - xy[(b * Nv + j) * 2 + 1];
        float d2 = dx * dx + dy * dy;
        int   sj = species[b * Nv + j];
        bool ia_j = (sj < 2), ip_j = (sj == 2);
        float bias = 0.0f;
        if (alive[b * Nv + j] == 0)            bias += NEGINF;
        if (d2 > R2)                           bias += NEGINF;
        if ((ia_i && ip_j) || (ip_i && ia_j))  bias += NEGINF;
        brow[j] = bias;
    }
}

// ----------------------------------------------------------------------------
// LayerNorm over D=512. 128 threads, 4 elems/thread. Two-pass (mean, then var)
// to match the reference formula exactly.
// outSel: 0 -> g_h, 1 -> outPtr (final output)
// ----------------------------------------------------------------------------
__global__ void __launch_bounds__(128)
ln_kernel(int inSel, int outSel, float* __restrict__ outPtr,
          const float* __restrict__ g, const float* __restrict__ be) {
    __shared__ float red[4];
    const float* in = selbuf(inSel);
    float* out = (outSel == 0) ? g_h : outPtr;
    int row = blockIdx.x;
    int t = threadIdx.x;
    const float* xr = in + (size_t)row * Dv;

    float v0 = xr[t], v1 = xr[t + 128], v2 = xr[t + 256], v3 = xr[t + 384];

    float s = v0 + v1 + v2 + v3;
    #pragma unroll
    for (int o = 16; o; o >>= 1) s += __shfl_xor_sync(0xffffffffu, s, o);
    if ((t & 31) == 0) red[t >> 5] = s;
    __syncthreads();
    float mean = (red[0] + red[1] + red[2] + red[3]) * (1.0f / Dv);
    __syncthreads();

    float d0 = v0 - mean, d1 = v1 - mean, d2 = v2 - mean, d3 = v3 - mean;
    float q = d0 * d0 + d1 * d1 + d2 * d2 + d3 * d3;
    #pragma unroll
    for (int o = 16; o; o >>= 1) q += __shfl_xor_sync(0xffffffffu, q, o);
    if ((t & 31) == 0) red[t >> 5] = q;
    __syncthreads();
    float var = (red[0] + red[1] + red[2] + red[3]) * (1.0f / Dv);
    float rs = rsqrtf(var + 1e-5f);

    float* orow = out + (size_t)row * Dv;
    orow[t      ] = d0 * rs * g[t      ] + be[t      ];
    orow[t + 128] = d1 * rs * g[t + 128] + be[t + 128];
    orow[t + 256] = d2 * rs * g[t + 256] + be[t + 256];
    orow[t + 384] = d3 * rs * g[t + 384] + be[t + 384];
}

// ----------------------------------------------------------------------------
// Generic NN GEMM: C[M,Nn] (op) A[M,K] @ W[K,Nn]
//   A, C contiguous with ld = K / Nn respectively; W row-major K x Nn.
//   EPI 0: C = acc
//   EPI 1: C = C + (acc + bias[n])        (residual)
//   EPI 2: C = gelu_exact(acc + bias[n])
// 64x64x16 tiles, 256 threads, 4x4 micro-tile.
// ----------------------------------------------------------------------------
template <int EPI>
__global__ void __launch_bounds__(256)
gemm_nn(int aSel, const float* __restrict__ W, int cSel,
        int M, int Nn, int K, const float* __restrict__ bias) {
    const float* A = selbuf(aSel);
    float* C = selbuf(cSel);

    __shared__ float As[16][65];
    __shared__ float Bs[16][64];

    const int tid = threadIdx.x;
    const int tx = tid & 15, ty = tid >> 4;
    const int m0 = blockIdx.y << 6;
    const int n0 = blockIdx.x << 6;
    const int ar = tid >> 2, ak = (tid & 3) << 2;   // A load: row, k-offset
    const int br = tid >> 4, bc = (tid & 15) << 2;  // B load: k-row, col

    const float* Ap = A + (size_t)(m0 + ar) * K + ak;
    const float* Bp = W + (size_t)br * Nn + (n0 + bc);

    float acc[4][4] = {};

    for (int k0 = 0; k0 < K; k0 += 16) {
        float4 a4 = *(const float4*)(Ap + k0);
        float4 b4 = *(const float4*)(Bp + (size_t)k0 * Nn);
        As[ak + 0][ar] = a4.x;
        As[ak + 1][ar] = a4.y;
        As[ak + 2][ar] = a4.z;
        As[ak + 3][ar] = a4.w;
        *(float4*)&Bs[br][bc] = b4;
        __syncthreads();

        #pragma unroll
        for (int kk = 0; kk < 16; kk++) {
            float a[4];
            #pragma unroll
            for (int i = 0; i < 4; i++) a[i] = As[kk][(ty << 2) + i];
            float4 bb = *(const float4*)&Bs[kk][tx << 2];
            float bvv[4] = {bb.x, bb.y, bb.z, bb.w};
            #pragma unroll
            for (int i = 0; i < 4; i++)
                #pragma unroll
                for (int j = 0; j < 4; j++)
                    acc[i][j] = fmaf(a[i], bvv[j], acc[i][j]);
        }
        __syncthreads();
    }

    const int cm = m0 + (ty << 2);
    const int cn = n0 + (tx << 2);
    #pragma unroll
    for (int i = 0; i < 4; i++) {
        float* Crow = C + (size_t)(cm + i) * Nn + cn;
        #pragma unroll
        for (int j = 0; j < 4; j++) {
            float v = acc[i][j];
            if (EPI == 0) {
                Crow[j] = v;
            } else if (EPI == 1) {
                Crow[j] = Crow[j] + (v + bias[cn + j]);
            } else {  // gelu (exact, erf-based)
                float u = v + bias[cn + j];
                Crow[j] = 0.5f * u * (1.0f + erff(u * 0.70710678118654752f));
            }
        }
    }
}

// ----------------------------------------------------------------------------
// Scores: S[z, i, j] = (Q_z[i,:] . K_z[j,:]) * 0.125 + bias[b, i, j]
// z = b*H + h. Q/K rows have ld = D with column offset h*DH. K over DH=64.
// ----------------------------------------------------------------------------
__global__ void __launch_bounds__(256)
gemm_nt_scores() {
    const int z = blockIdx.z;
    const int bb = z >> 3, hh = z & 7;
    const float* A  = g_q + (size_t)bb * Nv * Dv + hh * DHv;
    const float* Bm = g_k + (size_t)bb * Nv * Dv + hh * DHv;
    float* C = g_S + (size_t)z * Nv * Nv;
    const float* bias = g_bias + (size_t)bb * Nv * Nv;

    __shared__ float As[16][65];
    __shared__ float Bs[16][65];

    const int tid = threadIdx.x;
    const int tx = tid & 15, ty = tid >> 4;
    const int m0 = blockIdx.y << 6;
    const int n0 = blockIdx.x << 6;
    const int ar = tid >> 2, ak = (tid & 3) << 2;

    float acc[4][4] = {};

    for (int k0 = 0; k0 < DHv; k0 += 16) {
        float4 a4 = *(const float4*)(A  + (size_t)(m0 + ar) * Dv + k0 + ak);
        float4 b4 = *(const float4*)(Bm + (size_t)(n0 + ar) * Dv + k0 + ak);
        As[ak + 0][ar] = a4.x;  As[ak + 1][ar] = a4.y;
        As[ak + 2][ar] = a4.z;  As[ak + 3][ar] = a4.w;
        Bs[ak + 0][ar] = b4.x;  Bs[ak + 1][ar] = b4.y;
        Bs[ak + 2][ar] = b4.z;  Bs[ak + 3][ar] = b4.w;
        __syncthreads();

        #pragma unroll
        for (int kk = 0; kk < 16; kk++) {
            float a[4], bvv[4];
            #pragma unroll
            for (int i = 0; i < 4; i++) a[i]   = As[kk][(ty << 2) + i];
            #pragma unroll
            for (int j = 0; j < 4; j++) bvv[j] = Bs[kk][(tx << 2) + j];
            #pragma unroll
            for (int i = 0; i < 4; i++)
                #pragma unroll
                for (int j = 0; j < 4; j++)
                    acc[i][j] = fmaf(a[i], bvv[j], acc[i][j]);
        }
        __syncthreads();
    }

    const int cm = m0 + (ty << 2);
    const int cn = n0 + (tx << 2);
    #pragma unroll
    for (int i = 0; i < 4; i++) {
        float* Crow = C + (size_t)(cm + i) * Nv + cn;
        const float* brow = bias + (size_t)(cm + i) * Nv + cn;
        #pragma unroll
        for (int j = 0; j < 4; j++)
            Crow[j] = acc[i][j] * 0.125f + brow[j];
    }
}

// ----------------------------------------------------------------------------
// Row softmax over N=1024 (in place on g_S). One block per row, 256 threads.
// ----------------------------------------------------------------------------
__global__ void __launch_bounds__(256)
softmax_kernel() {
    __shared__ float red[8];
    const size_t row = blockIdx.x;
    float* r = g_S + row * Nv;
    const int t = threadIdx.x;

    float v0 = r[t], v1 = r[t + 256], v2 = r[t + 512], v3 = r[t + 768];

    float m = fmaxf(fmaxf(v0, v1), fmaxf(v2, v3));
    #pragma unroll
    for (int o = 16; o; o >>= 1) m = fmaxf(m, __shfl_xor_sync(0xffffffffu, m, o));
    if ((t & 31) == 0) red[t >> 5] = m;
    __syncthreads();
    m = red[0];
    #pragma unroll
    for (int w = 1; w < 8; w++) m = fmaxf(m, red[w]);
    __syncthreads();

    v0 = expf(v0 - m); v1 = expf(v1 - m); v2 = expf(v2 - m); v3 = expf(v3 - m);
    float s = v0 + v1 + v2 + v3;
    #pragma unroll
    for (int o = 16; o; o >>= 1) s += __shfl_xor_sync(0xffffffffu, s, o);
    if ((t & 31) == 0) red[t >> 5] = s;
    __syncthreads();
    float total = red[0] + red[1] + red[2] + red[3]
                + red[4] + red[5] + red[6] + red[7];
    float inv = 1.0f / total;

    r[t      ] = v0 * inv;
    r[t + 256] = v1 * inv;
    r[t + 512] = v2 * inv;
    r[t + 768] = v3 * inv;
}

// ----------------------------------------------------------------------------
// O = P @ V per (b,h): P is [N,N] (ld N), V columns h*DH..h*DH+63 (ld D).
// Output into g_o at the same column slice. M=1024, Nn=64, K=1024.
// ----------------------------------------------------------------------------
__global__ void __launch_bounds__(256)
gemm_pv() {
    const int z = blockIdx.z;
    const int bb = z >> 3, hh = z & 7;
    const float* A  = g_S + (size_t)z * Nv * Nv;
    const float* Bm = g_v + (size_t)bb * Nv * Dv + hh * DHv;
    float* C = g_o + (size_t)bb * Nv * Dv + hh * DHv;

    __shared__ float As[16][65];
    __shared__ float Bs[16][64];

    const int tid = threadIdx.x;
    const int tx = tid & 15, ty = tid >> 4;
    const int m0 = blockIdx.x << 6;   // 16 m-tiles
    const int ar = tid >> 2, ak = (tid & 3) << 2;
    const int br = tid >> 4, bc = (tid & 15) << 2;

    float acc[4][4] = {};

    for (int k0 = 0; k0 < Nv; k0 += 16) {
        float4 a4 = *(const float4*)(A + (size_t)(m0 + ar) * Nv + k0 + ak);
        float4 b4 = *(const float4*)(Bm + (size_t)(k0 + br) * Dv + bc);
        As[ak + 0][ar] = a4.x;  As[ak + 1][ar] = a4.y;
        As[ak + 2][ar] = a4.z;  As[ak + 3][ar] = a4.w;
        *(float4*)&Bs[br][bc] = b4;
        __syncthreads();

        #pragma unroll
        for (int kk = 0; kk < 16; kk++) {
            float a[4];
            #pragma unroll
            for (int i = 0; i < 4; i++) a[i] = As[kk][(ty << 2) + i];
            float4 bb4 = *(const float4*)&Bs[kk][tx << 2];
            float bvv[4] = {bb4.x, bb4.y, bb4.z, bb4.w};
            #pragma unroll
            for (int i = 0; i < 4; i++)
                #pragma unroll
                for (int j = 0; j < 4; j++)
                    acc[i][j] = fmaf(a[i], bvv[j], acc[i][j]);
        }
        __syncthreads();
    }

    const int cm = m0 + (ty << 2);
    const int cn = tx << 2;
    #pragma unroll
    for (int i = 0; i < 4; i++) {
        float* Crow = C + (size_t)(cm + i) * Dv + cn;
        #pragma unroll
        for (int j = 0; j < 4; j++) Crow[j] = acc[i][j];
    }
}

// ============================================================================
// Launch sequence (graph-capturable: kernel launches on default stream only)
// ============================================================================
extern "C" void kernel_launch(void* const* d_in, const int* in_sizes, int n_in,
                              void* d_out, int out_size) {
    const float* tokens = (const float*)d_in[0];
    const float* xy     = (const float*)d_in[1];
    const float* Wq     = (const float*)d_in[2];
    const float* Wk     = (const float*)d_in[3];
    const float* Wv     = (const float*)d_in[4];
    const float* Wo     = (const float*)d_in[5];
    const float* bo     = (const float*)d_in[6];
    const float* W1     = (const float*)d_in[7];
    const float* b1     = (const float*)d_in[8];
    const float* W2     = (const float*)d_in[9];
    const float* b2     = (const float*)d_in[10];
    const float* g1     = (const float*)d_in[11];
    const float* be1    = (const float*)d_in[12];
    const float* g2     = (const float*)d_in[13];
    const float* be2    = (const float*)d_in[14];
    const float* gf     = (const float*)d_in[15];
    const float* bf     = (const float*)d_in[16];
    const int*   alive  = (const int*)d_in[17];
    const int*   species= (const int*)d_in[18];
    float* out = (float*)d_out;

    copy_tokens<<<(ROWS * Dv / 4) / 256, 256>>>((const float4*)tokens);
    build_bias<<<dim3(Nv, Bv), 256>>>(xy, alive, species);

    for (int l = 0; l < Lv; l++) {
        // ln1: x -> h
        ln_kernel<<<ROWS, 128>>>(6, 0, nullptr, g1 + l * Dv, be1 + l * Dv);
        // Q/K/V projections: h @ W -> q,k,v
        gemm_nn<0><<<dim3(Dv / 64, ROWS / 64), 256>>>(0, Wq + (size_t)l * Dv * Dv, 3, ROWS, Dv, Dv, nullptr);
        gemm_nn<0><<<dim3(Dv / 64, ROWS / 64), 256>>>(0, Wk + (size_t)l * Dv * Dv, 4, ROWS, Dv, Dv, nullptr);
        gemm_nn<0><<<dim3(Dv / 64, ROWS / 64), 256>>>(0, Wv + (size_t)l * Dv * Dv, 5, ROWS, Dv, Dv, nullptr);
        // S = QK^T * 0.125 + bias
        gemm_nt_scores<<<dim3(Nv / 64, Nv / 64, Bv * Hv), 256>>>();
        // softmax rows of S (in place)
        softmax_kernel<<<Bv * Hv * Nv, 256>>>();
        // O = P V
        gemm_pv<<<dim3(Nv / 64, 1, Bv * Hv), 256>>>();
        // x += O Wo + bo
        gemm_nn<1><<<dim3(Dv / 64, ROWS / 64), 256>>>(1, Wo + (size_t)l * Dv * Dv, 6, ROWS, Dv, Dv, bo + l * Dv);
        // ln2: x -> h
        ln_kernel<<<ROWS, 128>>>(6, 0, nullptr, g2 + l * Dv, be2 + l * Dv);
        // ff = gelu(h W1 + b1)
        gemm_nn<2><<<dim3(DFFv / 64, ROWS / 64), 256>>>(0, W1 + (size_t)l * Dv * DFFv, 2, ROWS, DFFv, Dv, b1 + l * DFFv);
        // x += ff W2 + b2
        gemm_nn<1><<<dim3(Dv / 64, ROWS / 64), 256>>>(2, W2 + (size_t)l * DFFv * Dv, 6, ROWS, Dv, DFFv, b2 + l * Dv);
    }

    // final layernorm -> out
    ln_kernel<<<ROWS, 128>>>(6, 1, out, gf, bf);
}

// round 2
// speedup vs baseline: 2.1732x; 2.1732x over previous
#include <cuda_runtime.h>
#include <math.h>
#include <stdint.h>

// ============================================================================
// EcosystemTransformer — tf32 tensor-core version (mma.sync m16n8k8)
//   B=4, N=1024, D=512, H=8, L=6, DFF=2048, DH=64
// ============================================================================

namespace {
constexpr int Bv   = 4;
constexpr int Nv   = 1024;
constexpr int Dv   = 512;
constexpr int Hv   = 8;
constexpr int Lv   = 6;
constexpr int DFFv = 2048;
constexpr int DHv  = 64;
constexpr int ROWS = Bv * Nv;           // 4096
constexpr float NEGINF = -1000000000.0f;
constexpr float R2 = 100.0f;

constexpr int BM  = 128;
constexpr int BK  = 16;
constexpr int AST = 20;                 // A smem stride (conflict-free for frag loads)
}

// Scratch buffers (static __device__ globals: allocation-guard safe)
__device__ float g_x [ROWS * Dv];
__device__ float g_h [ROWS * Dv];
__device__ float g_q [ROWS * Dv];
__device__ float g_k [ROWS * Dv];
__device__ float g_v [ROWS * Dv];
__device__ float g_o [ROWS * Dv];
__device__ float g_ff[ROWS * DFFv];
__device__ float g_S [(size_t)Bv * Hv * Nv * Nv];   // 128 MB scores/probs
__device__ float g_bias[(size_t)Bv * Nv * Nv];      // 16 MB additive bias

__device__ __forceinline__ float* selbuf(int s) {
    switch (s) {
        case 0: return g_h;
        case 1: return g_o;
        case 2: return g_ff;
        case 3: return g_q;
        case 4: return g_k;
        case 5: return g_v;
        default: return g_x;
    }
}

// ---------------------------------------------------------------------------
// helpers
// ---------------------------------------------------------------------------
__device__ __forceinline__ float to_tf32(float x) {
    uint32_t u;
    asm("cvt.rna.tf32.f32 %0, %1;" : "=r"(u) : "f"(x));
    return __uint_as_float(u);
}
__device__ __forceinline__ float4 to_tf32_4(float4 v) {
    return make_float4(to_tf32(v.x), to_tf32(v.y), to_tf32(v.z), to_tf32(v.w));
}

__device__ __forceinline__ void mma_tf32(float c[4], const uint32_t a[4],
                                         uint32_t b0, uint32_t b1) {
    asm volatile(
        "mma.sync.aligned.m16n8k8.row.col.f32.tf32.tf32.f32 "
        "{%0,%1,%2,%3}, {%4,%5,%6,%7}, {%8,%9}, {%0,%1,%2,%3};"
        : "+f"(c[0]), "+f"(c[1]), "+f"(c[2]), "+f"(c[3])
        : "r"(a[0]), "r"(a[1]), "r"(a[2]), "r"(a[3]), "r"(b0), "r"(b1));
}

// compute one BK=16 slab: acc[2][NT][4], warp tile 32 x (NT*8)
template <int NT, int BST>
__device__ __forceinline__ void compute_bk(const float* __restrict__ As,
                                           const float* __restrict__ Bs,
                                           float acc[2][NT][4],
                                           int lane, int warpM, int warpN) {
    const int gid = lane >> 2, tig = lane & 3;
    #pragma unroll
    for (int kk = 0; kk < 16; kk += 8) {
        uint32_t a[2][4];
        #pragma unroll
        for (int mt = 0; mt < 2; mt++) {
            const int m = warpM + mt * 16;
            a[mt][0] = __float_as_uint(As[(m + gid)     * AST + kk + tig]);
            a[mt][1] = __float_as_uint(As[(m + gid + 8) * AST + kk + tig]);
            a[mt][2] = __float_as_uint(As[(m + gid)     * AST + kk + tig + 4]);
            a[mt][3] = __float_as_uint(As[(m + gid + 8) * AST + kk + tig + 4]);
        }
        #pragma unroll
        for (int nt = 0; nt < NT; nt++) {
            const int n = warpN + nt * 8 + gid;
            uint32_t b0 = __float_as_uint(Bs[(kk + tig)     * BST + n]);
            uint32_t b1 = __float_as_uint(Bs[(kk + tig + 4) * BST + n]);
            mma_tf32(acc[0][nt], a[0], b0, b1);
            mma_tf32(acc[1][nt], a[1], b0, b1);
        }
    }
}

// ----------------------------------------------------------------------------
// tokens -> g_x
// ----------------------------------------------------------------------------
__global__ void __launch_bounds__(256)
copy_tokens(const float4* __restrict__ tokens) {
    int i = blockIdx.x * 256 + threadIdx.x;
    ((float4*)g_x)[i] = tokens[i];
}

// ----------------------------------------------------------------------------
// Additive attention bias (B,N,N)
// ----------------------------------------------------------------------------
__global__ void __launch_bounds__(256)
build_bias(const float* __restrict__ xy,
           const int*   __restrict__ alive,
           const int*   __restrict__ species) {
    int i = blockIdx.x;
    int b = blockIdx.y;
    float xi = xy[(b * Nv + i) * 2 + 0];
    float yi = xy[(b * Nv + i) * 2 + 1];
    int   si = species[b * Nv + i];
    bool ia_i = (si < 2), ip_i = (si == 2);
    float* brow = g_bias + ((size_t)b * Nv + i) * Nv;
    for (int j = threadIdx.x; j < Nv; j += 256) {
        float dx = xi - xy[(b * Nv + j) * 2 + 0];
        float dy = yi - xy[(b * Nv + j) * 2 + 1];
        float d2 = dx * dx + dy * dy;
        int   sj = species[b * Nv + j];
        bool ia_j = (sj < 2), ip_j = (sj == 2);
        float bias = 0.0f;
        if (alive[b * Nv + j] == 0)            bias += NEGINF;
        if (d2 > R2)                           bias += NEGINF;
        if ((ia_i && ip_j) || (ip_i && ia_j))  bias += NEGINF;
        brow[j] = bias;
    }
}

// ----------------------------------------------------------------------------
// LayerNorm over D=512
// ----------------------------------------------------------------------------
__global__ void __launch_bounds__(128)
ln_kernel(int inSel, int outSel, float* __restrict__ outPtr,
          const float* __restrict__ g, const float* __restrict__ be) {
    __shared__ float red[4];
    const float* in = selbuf(inSel);
    float* out = (outSel == 0) ? g_h : outPtr;
    int row = blockIdx.x;
    int t = threadIdx.x;
    const float* xr = in + (size_t)row * Dv;

    float v0 = xr[t], v1 = xr[t + 128], v2 = xr[t + 256], v3 = xr[t + 384];

    float s = v0 + v1 + v2 + v3;
    #pragma unroll
    for (int o = 16; o; o >>= 1) s += __shfl_xor_sync(0xffffffffu, s, o);
    if ((t & 31) == 0) red[t >> 5] = s;
    __syncthreads();
    float mean = (red[0] + red[1] + red[2] + red[3]) * (1.0f / Dv);
    __syncthreads();

    float d0 = v0 - mean, d1 = v1 - mean, d2 = v2 - mean, d3 = v3 - mean;
    float q = d0 * d0 + d1 * d1 + d2 * d2 + d3 * d3;
    #pragma unroll
    for (int o = 16; o; o >>= 1) q += __shfl_xor_sync(0xffffffffu, q, o);
    if ((t & 31) == 0) red[t >> 5] = q;
    __syncthreads();
    float var = (red[0] + red[1] + red[2] + red[3]) * (1.0f / Dv);
    float rs = rsqrtf(var + 1e-5f);

    float* orow = out + (size_t)row * Dv;
    orow[t      ] = d0 * rs * g[t      ] + be[t      ];
    orow[t + 128] = d1 * rs * g[t + 128] + be[t + 128];
    orow[t + 256] = d2 * rs * g[t + 256] + be[t + 256];
    orow[t + 384] = d3 * rs * g[t + 384] + be[t + 384];
}

// ----------------------------------------------------------------------------
// Tensor-core NN GEMM: C[M,Nn] (op) A[M,K] @ W[K,Nn].  BM=128, BN=128, BK=16.
//   EPI 0: C = acc;  EPI 1: C += acc + bias[n];  EPI 2: C = gelu(acc + bias[n])
// ----------------------------------------------------------------------------
template <int EPI>
__global__ void __launch_bounds__(256)
gemm_tc(int aSel, const float* __restrict__ W, int cSel,
        int M, int Nn, int K, const float* __restrict__ bias) {
    constexpr int BN  = 128;
    constexpr int BST = BN + 8;   // 136
    constexpr int NT  = BN / 16;  // 8

    const float* A = selbuf(aSel);
    float* C = selbuf(cSel);

    __shared__ float As[BM * AST];
    __shared__ float Bs[BK * BST];

    const int tid  = threadIdx.x;
    const int lane = tid & 31;
    const int wid  = tid >> 5;
    const int warpM = (wid & 3) * 32;
    const int warpN = (wid >> 2) * (BN / 2);
    const int m0 = blockIdx.y * BM;
    const int n0 = blockIdx.x * BN;

    // loader coords
    const int arow = tid >> 2, ac4 = tid & 3;             // A: 2 slots (tid, tid+256)
    const int arow2 = (tid + 256) >> 2, ac42 = ac4;       // (tid+256)&3 == tid&3
    const int brow = tid >> 5, bc4 = tid & 31;            // B: 2 slots
    const int brow2 = (tid + 256) >> 5, bc42 = bc4;

    const float* Ag = A + (size_t)m0 * K;
    const float* Bg = W + n0;

    float acc[2][NT][4] = {};

    // preload tile 0
    {
        float4 a0 = *(const float4*)(Ag + (size_t)arow  * K + ac4  * 4);
        float4 a1 = *(const float4*)(Ag + (size_t)arow2 * K + ac42 * 4);
        float4 b0 = *(const float4*)(Bg + (size_t)brow  * Nn + bc4  * 4);
        float4 b1 = *(const float4*)(Bg + (size_t)brow2 * Nn + bc42 * 4);
        *(float4*)&As[arow  * AST + ac4  * 4] = to_tf32_4(a0);
        *(float4*)&As[arow2 * AST + ac42 * 4] = to_tf32_4(a1);
        *(float4*)&Bs[brow  * BST + bc4  * 4] = to_tf32_4(b0);
        *(float4*)&Bs[brow2 * BST + bc42 * 4] = to_tf32_4(b1);
    }
    __syncthreads();

    for (int k0 = 0; k0 < K; k0 += BK) {
        const bool has_next = (k0 + BK) < K;
        float4 pa0, pa1, pb0, pb1;
        if (has_next) {
            const int kn = k0 + BK;
            pa0 = *(const float4*)(Ag + (size_t)arow  * K + kn + ac4  * 4);
            pa1 = *(const float4*)(Ag + (size_t)arow2 * K + kn + ac42 * 4);
            pb0 = *(const float4*)(Bg + (size_t)(kn + brow ) * Nn + bc4  * 4);
            pb1 = *(const float4*)(Bg + (size_t)(kn + brow2) * Nn + bc42 * 4);
        }

        compute_bk<NT, BST>(As, Bs, acc, lane, warpM, warpN);
        __syncthreads();

        if (has_next) {
            *(float4*)&As[arow  * AST + ac4  * 4] = to_tf32_4(pa0);
            *(float4*)&As[arow2 * AST + ac42 * 4] = to_tf32_4(pa1);
            *(float4*)&Bs[brow  * BST + bc4  * 4] = to_tf32_4(pb0);
            *(float4*)&Bs[brow2 * BST + bc42 * 4] = to_tf32_4(pb1);
        }
        __syncthreads();
    }

    // epilogue
    const int gid = lane >> 2, tig = lane & 3;
    #pragma unroll
    for (int mt = 0; mt < 2; mt++) {
        #pragma unroll
        for (int half = 0; half < 2; half++) {
            const int row = m0 + warpM + mt * 16 + gid + half * 8;
            #pragma unroll
            for (int nt = 0; nt < NT; nt++) {
                const int col = n0 + warpN + nt * 8 + 2 * tig;
                float v0 = acc[mt][nt][half * 2 + 0];
                float v1 = acc[mt][nt][half * 2 + 1];
                float* Cp = C + (size_t)row * Nn + col;
                if (EPI == 0) {
                    Cp[0] = v0; Cp[1] = v1;
                } else if (EPI == 1) {
                    Cp[0] = Cp[0] + (v0 + bias[col]);
                    Cp[1] = Cp[1] + (v1 + bias[col + 1]);
                } else {
                    float u0 = v0 + bias[col];
                    float u1 = v1 + bias[col + 1];
                    Cp[0] = 0.5f * u0 * (1.0f + erff(u0 * 0.70710678118654752f));
                    Cp[1] = 0.5f * u1 * (1.0f + erff(u1 * 0.70710678118654752f));
                }
            }
        }
    }
}

// ----------------------------------------------------------------------------
// Scores: S[z,i,j] = (Q_z[i,:] . K_z[j,:]) * 0.125 + bias[b,i,j]
// NT GEMM on tensor cores: K matrix transposed into smem. K-dim = 64.
// ----------------------------------------------------------------------------
__global__ void __launch_bounds__(256)
gemm_scores_tc() {
    constexpr int BN  = 128;
    constexpr int BST = BN + 8;
    constexpr int NT  = BN / 16;

    const int z = blockIdx.z;
    const int bb = z >> 3, hh = z & 7;
    const float* Ag = g_q + (size_t)bb * Nv * Dv + hh * DHv;   // lda = Dv
    const float* Bg = g_k + (size_t)bb * Nv * Dv + hh * DHv;   // ldb = Dv, [N][K]
    float* C = g_S + (size_t)z * Nv * Nv;
    const float* biasM = g_bias + (size_t)bb * Nv * Nv;

    __shared__ float As[BM * AST];
    __shared__ float Bs[BK * BST];

    const int tid  = threadIdx.x;
    const int lane = tid & 31;
    const int wid  = tid >> 5;
    const int warpM = (wid & 3) * 32;
    const int warpN = (wid >> 2) * (BN / 2);
    const int m0 = blockIdx.y * BM;
    const int n0 = blockIdx.x * BN;

    const int arow = tid >> 2, ac4 = tid & 3;
    const int arow2 = (tid + 256) >> 2;
    // B NT loader: slot s -> n = s>>2, k4 = s&3, scatter-store transposed
    const int bn = tid >> 2, bk4 = tid & 3;
    const int bn2 = (tid + 256) >> 2;

    float acc[2][NT][4] = {};

    #pragma unroll 1
    for (int k0 = 0; k0 < DHv; k0 += BK) {
        float4 a0 = *(const float4*)(Ag + (size_t)(m0 + arow ) * Dv + k0 + ac4 * 4);
        float4 a1 = *(const float4*)(Ag + (size_t)(m0 + arow2) * Dv + k0 + ac4 * 4);
        float4 b0 = *(const float4*)(Bg + (size_t)(n0 + bn )  * Dv + k0 + bk4 * 4);
        float4 b1 = *(const float4*)(Bg + (size_t)(n0 + bn2)  * Dv + k0 + bk4 * 4);
        *(float4*)&As[arow  * AST + ac4 * 4] = to_tf32_4(a0);
        *(float4*)&As[arow2 * AST + ac4 * 4] = to_tf32_4(a1);
        Bs[(bk4 * 4 + 0) * BST + bn]  = to_tf32(b0.x);
        Bs[(bk4 * 4 + 1) * BST + bn]  = to_tf32(b0.y);
        Bs[(bk4 * 4 + 2) * BST + bn]  = to_tf32(b0.z);
        Bs[(bk4 * 4 + 3) * BST + bn]  = to_tf32(b0.w);
        Bs[(bk4 * 4 + 0) * BST + bn2] = to_tf32(b1.x);
        Bs[(bk4 * 4 + 1) * BST + bn2] = to_tf32(b1.y);
        Bs[(bk4 * 4 + 2) * BST + bn2] = to_tf32(b1.z);
        Bs[(bk4 * 4 + 3) * BST + bn2] = to_tf32(b1.w);
        __syncthreads();

        compute_bk<NT, BST>(As, Bs, acc, lane, warpM, warpN);
        __syncthreads();
    }

    const int gid = lane >> 2, tig = lane & 3;
    #pragma unroll
    for (int mt = 0; mt < 2; mt++) {
        #pragma unroll
        for (int half = 0; half < 2; half++) {
            const int row = m0 + warpM + mt * 16 + gid + half * 8;
            #pragma unroll
            for (int nt = 0; nt < NT; nt++) {
                const int col = n0 + warpN + nt * 8 + 2 * tig;
                const float* bp = biasM + (size_t)row * Nv + col;
                float* Cp = C + (size_t)row * Nv + col;
                Cp[0] = acc[mt][nt][half * 2 + 0] * 0.125f + bp[0];
                Cp[1] = acc[mt][nt][half * 2 + 1] * 0.125f + bp[1];
            }
        }
    }
}

// ----------------------------------------------------------------------------
// Row softmax over N=1024 (in place on g_S), float4-vectorized.
// ----------------------------------------------------------------------------
__global__ void __launch_bounds__(256)
softmax_kernel() {
    __shared__ float red[8];
    const size_t row = blockIdx.x;
    float4* r = (float4*)(g_S + row * Nv);
    const int t = threadIdx.x;

    float4 v = r[t];

    float m = fmaxf(fmaxf(v.x, v.y), fmaxf(v.z, v.w));
    #pragma unroll
    for (int o = 16; o; o >>= 1) m = fmaxf(m, __shfl_xor_sync(0xffffffffu, m, o));
    if ((t & 31) == 0) red[t >> 5] = m;
    __syncthreads();
    m = red[0];
    #pragma unroll
    for (int w = 1; w < 8; w++) m = fmaxf(m, red[w]);
    __syncthreads();

    v.x = expf(v.x - m); v.y = expf(v.y - m);
    v.z = expf(v.z - m); v.w = expf(v.w - m);
    float s = v.x + v.y + v.z + v.w;
    #pragma unroll
    for (int o = 16; o; o >>= 1) s += __shfl_xor_sync(0xffffffffu, s, o);
    if ((t & 31) == 0) red[t >> 5] = s;
    __syncthreads();
    float total = red[0] + red[1] + red[2] + red[3]
                + red[4] + red[5] + red[6] + red[7];
    float inv = 1.0f / total;

    v.x *= inv; v.y *= inv; v.z *= inv; v.w *= inv;
    r[t] = v;
}

// ----------------------------------------------------------------------------
// O = P @ V per (b,h). BM=128, BN=64, K=1024.  P ld=Nv, V/C ld=Dv.
// ----------------------------------------------------------------------------
__global__ void __launch_bounds__(256)
gemm_pv_tc() {
    constexpr int BN  = 64;
    constexpr int BST = BN + 8;   // 72
    constexpr int NT  = BN / 16;  // 4

    const int z = blockIdx.z;
    const int bb = z >> 3, hh = z & 7;
    const float* Ag = g_S + (size_t)z * Nv * Nv;                 // lda = Nv
    const float* Bg = g_v + (size_t)bb * Nv * Dv + hh * DHv;     // ldb = Dv
    float* C = g_o + (size_t)bb * Nv * Dv + hh * DHv;

    __shared__ float As[BM * AST];
    __shared__ float Bs[BK * BST];

    const int tid  = threadIdx.x;
    const int lane = tid & 31;
    const int wid  = tid >> 5;
    const int warpM = (wid & 3) * 32;
    const int warpN = (wid >> 2) * (BN / 2);
    const int m0 = blockIdx.y * BM;

    const int arow = tid >> 2, ac4 = tid & 3;
    const int arow2 = (tid + 256) >> 2;
    const int brow = tid >> 4, bc4 = tid & 15;   // 256 slots, 1 per thread

    float acc[2][NT][4] = {};

    // preload tile 0
    {
        float4 a0 = *(const float4*)(Ag + (size_t)(m0 + arow ) * Nv + ac4 * 4);
        float4 a1 = *(const float4*)(Ag + (size_t)(m0 + arow2) * Nv + ac4 * 4);
        float4 b0 = *(const float4*)(Bg + (size_t)brow * Dv + bc4 * 4);
        *(float4*)&As[arow  * AST + ac4 * 4] = to_tf32_4(a0);
        *(float4*)&As[arow2 * AST + ac4 * 4] = to_tf32_4(a1);
        *(float4*)&Bs[brow  * BST + bc4 * 4] = to_tf32_4(b0);
    }
    __syncthreads();

    for (int k0 = 0; k0 < Nv; k0 += BK) {
        const bool has_next = (k0 + BK) < Nv;
        float4 pa0, pa1, pb0;
        if (has_next) {
            const int kn = k0 + BK;
            pa0 = *(const float4*)(Ag + (size_t)(m0 + arow ) * Nv + kn + ac4 * 4);
            pa1 = *(const float4*)(Ag + (size_t)(m0 + arow2) * Nv + kn + ac4 * 4);
            pb0 = *(const float4*)(Bg + (size_t)(kn + brow) * Dv + bc4 * 4);
        }

        compute_bk<NT, BST>(As, Bs, acc, lane, warpM, warpN);
        __syncthreads();

        if (has_next) {
            *(float4*)&As[arow  * AST + ac4 * 4] = to_tf32_4(pa0);
            *(float4*)&As[arow2 * AST + ac4 * 4] = to_tf32_4(pa1);
            *(float4*)&Bs[brow  * BST + bc4 * 4] = to_tf32_4(pb0);
        }
        __syncthreads();
    }

    const int gid = lane >> 2, tig = lane & 3;
    #pragma unroll
    for (int mt = 0; mt < 2; mt++) {
        #pragma unroll
        for (int half = 0; half < 2; half++) {
            const int row = m0 + warpM + mt * 16 + gid + half * 8;
            #pragma unroll
            for (int nt = 0; nt < NT; nt++) {
                const int col = warpN + nt * 8 + 2 * tig;
                float* Cp = C + (size_t)row * Dv + col;
                Cp[0] = acc[mt][nt][half * 2 + 0];
                Cp[1] = acc[mt][nt][half * 2 + 1];
            }
        }
    }
}

// ============================================================================
// Launch sequence
// ============================================================================
extern "C" void kernel_launch(void* const* d_in, const int* in_sizes, int n_in,
                              void* d_out, int out_size) {
    const float* tokens = (const float*)d_in[0];
    const float* xy     = (const float*)d_in[1];
    const float* Wq     = (const float*)d_in[2];
    const float* Wk     = (const float*)d_in[3];
    const float* Wv     = (const float*)d_in[4];
    const float* Wo     = (const float*)d_in[5];
    const float* bo     = (const float*)d_in[6];
    const float* W1     = (const float*)d_in[7];
    const float* b1     = (const float*)d_in[8];
    const float* W2     = (const float*)d_in[9];
    const float* b2     = (const float*)d_in[10];
    const float* g1     = (const float*)d_in[11];
    const float* be1    = (const float*)d_in[12];
    const float* g2     = (const float*)d_in[13];
    const float* be2    = (const float*)d_in[14];
    const float* gf     = (const float*)d_in[15];
    const float* bf     = (const float*)d_in[16];
    const int*   alive  = (const int*)d_in[17];
    const int*   species= (const int*)d_in[18];
    float* out = (float*)d_out;

    copy_tokens<<<(ROWS * Dv / 4) / 256, 256>>>((const float4*)tokens);
    build_bias<<<dim3(Nv, Bv), 256>>>(xy, alive, species);

    for (int l = 0; l < Lv; l++) {
        // ln1: x -> h
        ln_kernel<<<ROWS, 128>>>(6, 0, nullptr, g1 + l * Dv, be1 + l * Dv);
        // Q/K/V projections: h @ W -> q,k,v
        gemm_tc<0><<<dim3(Dv / 128, ROWS / 128), 256>>>(0, Wq + (size_t)l * Dv * Dv, 3, ROWS, Dv, Dv, nullptr);
        gemm_tc<0><<<dim3(Dv / 128, ROWS / 128), 256>>>(0, Wk + (size_t)l * Dv * Dv, 4, ROWS, Dv, Dv, nullptr);
        gemm_tc<0><<<dim3(Dv / 128, ROWS / 128), 256>>>(0, Wv + (size_t)l * Dv * Dv, 5, ROWS, Dv, Dv, nullptr);
        // S = QK^T * 0.125 + bias
        gemm_scores_tc<<<dim3(Nv / 128, Nv / 128, Bv * Hv), 256>>>();
        // softmax rows of S (in place)
        softmax_kernel<<<Bv * Hv * Nv, 256>>>();
        // O = P V
        gemm_pv_tc<<<dim3(1, Nv / 128, Bv * Hv), 256>>>();
        // x += O Wo + bo
        gemm_tc<1><<<dim3(Dv / 128, ROWS / 128), 256>>>(1, Wo + (size_t)l * Dv * Dv, 6, ROWS, Dv, Dv, bo + l * Dv);
        // ln2: x -> h
        ln_kernel<<<ROWS, 128>>>(6, 0, nullptr, g2 + l * Dv, be2 + l * Dv);
        // ff = gelu(h W1 + b1)
        gemm_tc<2><<<dim3(DFFv / 128, ROWS / 128), 256>>>(0, W1 + (size_t)l * Dv * DFFv, 2, ROWS, DFFv, Dv, b1 + l * DFFv);
        // x += ff W2 + b2
        gemm_tc<1><<<dim3(Dv / 128, ROWS / 128), 256>>>(2, W2 + (size_t)l * DFFv * Dv, 6, ROWS, Dv, DFFv, b2 + l * Dv);
    }

    // final layernorm -> out
    ln_kernel<<<ROWS, 128>>>(6, 1, out, gf, bf);
}

// round 3
// speedup vs baseline: 3.1700x; 1.4587x over previous
#include <cuda_runtime.h>
#include <math.h>
#include <stdint.h>

// ============================================================================
// EcosystemTransformer — tf32 mma + cp.async double-buffered GEMM
//                        + fused flash attention (bias on the fly)
//   B=4, N=1024, D=512, H=8, L=6, DFF=2048, DH=64
// ============================================================================

namespace {
constexpr int Bv   = 4;
constexpr int Nv   = 1024;
constexpr int Dv   = 512;
constexpr int Lv   = 6;
constexpr int DFFv = 2048;
constexpr int DHv  = 64;
constexpr int ROWS = Bv * Nv;           // 4096
constexpr float NEGINF = -1000000000.0f;
constexpr float R2 = 100.0f;

constexpr int BM  = 128;
constexpr int BK  = 16;
constexpr int AST = 20;                 // A smem stride (conflict-free)
}

// Scratch buffers
__device__ __align__(16) float g_x [ROWS * Dv];
__device__ __align__(16) float g_h [ROWS * Dv];
__device__ __align__(16) float g_q [ROWS * Dv];
__device__ __align__(16) float g_k [ROWS * Dv];
__device__ __align__(16) float g_v [ROWS * Dv];
__device__ __align__(16) float g_o [ROWS * Dv];
__device__ __align__(16) float g_ff[ROWS * DFFv];

__device__ __forceinline__ float* selbuf(int s) {
    switch (s) {
        case 0: return g_h;
        case 1: return g_o;
        case 2: return g_ff;
        case 3: return g_q;
        case 4: return g_k;
        case 5: return g_v;
        default: return g_x;
    }
}

// ---------------------------------------------------------------------------
// helpers
// ---------------------------------------------------------------------------
__device__ __forceinline__ float to_tf32(float x) {
    uint32_t u;
    asm("cvt.rna.tf32.f32 %0, %1;" : "=r"(u) : "f"(x));
    return __uint_as_float(u);
}

__device__ __forceinline__ void cp_async16(void* smem_dst, const void* gmem_src) {
    uint32_t s = (uint32_t)__cvta_generic_to_shared(smem_dst);
    asm volatile("cp.async.ca.shared.global [%0], [%1], 16;\n"
                 :: "r"(s), "l"(__cvta_generic_to_global(gmem_src)) : "memory");
}
__device__ __forceinline__ void cp_commit() {
    asm volatile("cp.async.commit_group;\n" ::: "memory");
}
template <int N>
__device__ __forceinline__ void cp_wait() {
    asm volatile("cp.async.wait_group %0;\n" :: "n"(N) : "memory");
}

__device__ __forceinline__ void mma_tf32(float c[4], const uint32_t a[4],
                                         uint32_t b0, uint32_t b1) {
    asm volatile(
        "mma.sync.aligned.m16n8k8.row.col.f32.tf32.tf32.f32 "
        "{%0,%1,%2,%3}, {%4,%5,%6,%7}, {%8,%9}, {%0,%1,%2,%3};"
        : "+f"(c[0]), "+f"(c[1]), "+f"(c[2]), "+f"(c[3])
        : "r"(a[0]), "r"(a[1]), "r"(a[2]), "r"(a[3]), "r"(b0), "r"(b1));
}

// one BK=16 slab: warp tile 32 x (NT*8), acc[2][NT][4]
template <int NT, int BST>
__device__ __forceinline__ void compute_bk(const float* __restrict__ As,
                                           const float* __restrict__ Bs,
                                           float acc[2][NT][4],
                                           int lane, int warpM, int warpN) {
    const int gid = lane >> 2, tig = lane & 3;
    #pragma unroll
    for (int kk = 0; kk < 16; kk += 8) {
        uint32_t a[2][4];
        #pragma unroll
        for (int mt = 0; mt < 2; mt++) {
            const int m = warpM + mt * 16;
            a[mt][0] = __float_as_uint(As[(m + gid)     * AST + kk + tig]);
            a[mt][1] = __float_as_uint(As[(m + gid + 8) * AST + kk + tig]);
            a[mt][2] = __float_as_uint(As[(m + gid)     * AST + kk + tig + 4]);
            a[mt][3] = __float_as_uint(As[(m + gid + 8) * AST + kk + tig + 4]);
        }
        #pragma unroll
        for (int nt = 0; nt < NT; nt++) {
            const int n = warpN + nt * 8 + gid;
            uint32_t b0 = __float_as_uint(Bs[(kk + tig)     * BST + n]);
            uint32_t b1 = __float_as_uint(Bs[(kk + tig + 4) * BST + n]);
            mma_tf32(acc[0][nt], a[0], b0, b1);
            mma_tf32(acc[1][nt], a[1], b0, b1);
        }
    }
}

// 64-K slab, single 16-row m-tile (flash attention): acc[NT][4]
template <int NT>
__device__ __forceinline__ void mma_slab64(const float* __restrict__ As, int ast,
                                           const float* __restrict__ Bs, int bst,
                                           float acc[NT][4], int lane, int rowBase) {
    const int gid = lane >> 2, tig = lane & 3;
    #pragma unroll
    for (int kk = 0; kk < 64; kk += 8) {
        uint32_t a[4];
        a[0] = __float_as_uint(As[(rowBase + gid)     * ast + kk + tig]);
        a[1] = __float_as_uint(As[(rowBase + gid + 8) * ast + kk + tig]);
        a[2] = __float_as_uint(As[(rowBase + gid)     * ast + kk + tig + 4]);
        a[3] = __float_as_uint(As[(rowBase + gid + 8) * ast + kk + tig + 4]);
        #pragma unroll
        for (int nt = 0; nt < NT; nt++) {
            uint32_t b0 = __float_as_uint(Bs[(kk + tig)     * bst + nt * 8 + gid]);
            uint32_t b1 = __float_as_uint(Bs[(kk + tig + 4) * bst + nt * 8 + gid]);
            mma_tf32(acc[nt], a, b0, b1);
        }
    }
}

// ----------------------------------------------------------------------------
// tokens -> g_x
// ----------------------------------------------------------------------------
__global__ void __launch_bounds__(256)
copy_tokens(const float4* __restrict__ tokens) {
    int i = blockIdx.x * 256 + threadIdx.x;
    ((float4*)g_x)[i] = tokens[i];
}

// ----------------------------------------------------------------------------
// LayerNorm over D=512
// ----------------------------------------------------------------------------
__global__ void __launch_bounds__(128)
ln_kernel(int inSel, int outSel, float* __restrict__ outPtr,
          const float* __restrict__ g, const float* __restrict__ be) {
    __shared__ float red[4];
    const float* in = selbuf(inSel);
    float* out = (outSel == 0) ? g_h : outPtr;
    int row = blockIdx.x;
    int t = threadIdx.x;
    const float* xr = in + (size_t)row * Dv;

    float v0 = xr[t], v1 = xr[t + 128], v2 = xr[t + 256], v3 = xr[t + 384];

    float s = v0 + v1 + v2 + v3;
    #pragma unroll
    for (int o = 16; o; o >>= 1) s += __shfl_xor_sync(0xffffffffu, s, o);
    if ((t & 31) == 0) red[t >> 5] = s;
    __syncthreads();
    float mean = (red[0] + red[1] + red[2] + red[3]) * (1.0f / Dv);
    __syncthreads();

    float d0 = v0 - mean, d1 = v1 - mean, d2 = v2 - mean, d3 = v3 - mean;
    float q = d0 * d0 + d1 * d1 + d2 * d2 + d3 * d3;
    #pragma unroll
    for (int o = 16; o; o >>= 1) q += __shfl_xor_sync(0xffffffffu, q, o);
    if ((t & 31) == 0) red[t >> 5] = q;
    __syncthreads();
    float var = (red[0] + red[1] + red[2] + red[3]) * (1.0f / Dv);
    float rs = rsqrtf(var + 1e-5f);

    float* orow = out + (size_t)row * Dv;
    orow[t      ] = d0 * rs * g[t      ] + be[t      ];
    orow[t + 128] = d1 * rs * g[t + 128] + be[t + 128];
    orow[t + 256] = d2 * rs * g[t + 256] + be[t + 256];
    orow[t + 384] = d3 * rs * g[t + 384] + be[t + 384];
}

// ----------------------------------------------------------------------------
// cp.async double-buffered tensor-core NN GEMM.
// blockIdx.z selects among W0/W1/W2 and output selbuf(cSelBase + z).
//   EPI 0: C = acc;  EPI 1: C += acc + bias[n];  EPI 2: C = gelu(acc + bias[n])
// ----------------------------------------------------------------------------
template <int EPI>
__global__ void __launch_bounds__(256)
gemm2(int aSel, const float* __restrict__ W0, const float* __restrict__ W1,
      const float* __restrict__ W2, int cSelBase, int M, int Nn, int K,
      const float* __restrict__ bias) {
    constexpr int BN  = 128;
    constexpr int BST = BN + 8;   // 136
    constexpr int NT  = BN / 16;  // 8

    const int z = blockIdx.z;
    const float* W = (z == 0) ? W0 : (z == 1) ? W1 : W2;
    const float* A = selbuf(aSel);
    float* C = selbuf(cSelBase + z);

    __shared__ float As[2][BM * AST];
    __shared__ float Bs[2][BK * BST];

    const int tid  = threadIdx.x;
    const int lane = tid & 31;
    const int wid  = tid >> 5;
    const int warpM = (wid & 3) * 32;
    const int warpN = (wid >> 2) * (BN / 2);
    const int m0 = blockIdx.y * BM;
    const int n0 = blockIdx.x * BN;

    const int arow  = tid >> 2, ac4 = tid & 3;
    const int arow2 = arow + 64;
    const int brow  = tid >> 5, bc4 = tid & 31;
    const int brow2 = brow + 8;

    const float* Ag = A + (size_t)m0 * K;
    const float* Bg = W + n0;

    auto load_stage = [&](int buf, int k0) {
        cp_async16(&As[buf][arow  * AST + ac4 * 4], Ag + (size_t)arow  * K + k0 + ac4 * 4);
        cp_async16(&As[buf][arow2 * AST + ac4 * 4], Ag + (size_t)arow2 * K + k0 + ac4 * 4);
        cp_async16(&Bs[buf][brow  * BST + bc4 * 4], Bg + (size_t)(k0 + brow ) * Nn + bc4 * 4);
        cp_async16(&Bs[buf][brow2 * BST + bc4 * 4], Bg + (size_t)(k0 + brow2) * Nn + bc4 * 4);
        cp_commit();
    };

    float acc[2][NT][4] = {};

    load_stage(0, 0);
    const int T = K / BK;
    for (int i = 0; i < T; i++) {
        if (i + 1 < T) {
            load_stage((i + 1) & 1, (i + 1) * BK);
            cp_wait<1>();
        } else {
            cp_wait<0>();
        }
        __syncthreads();
        compute_bk<NT, BST>(As[i & 1], Bs[i & 1], acc, lane, warpM, warpN);
        __syncthreads();
    }

    const int gid = lane >> 2, tig = lane & 3;
    #pragma unroll
    for (int mt = 0; mt < 2; mt++) {
        #pragma unroll
        for (int half = 0; half < 2; half++) {
            const int row = m0 + warpM + mt * 16 + gid + half * 8;
            #pragma unroll
            for (int nt = 0; nt < NT; nt++) {
                const int col = n0 + warpN + nt * 8 + 2 * tig;
                float v0 = acc[mt][nt][half * 2 + 0];
                float v1 = acc[mt][nt][half * 2 + 1];
                float* Cp = C + (size_t)row * Nn + col;
                if (EPI == 0) {
                    Cp[0] = v0; Cp[1] = v1;
                } else if (EPI == 1) {
                    Cp[0] = Cp[0] + (v0 + bias[col]);
                    Cp[1] = Cp[1] + (v1 + bias[col + 1]);
                } else {
                    float u0 = v0 + bias[col];
                    float u1 = v1 + bias[col + 1];
                    Cp[0] = 0.5f * u0 * (1.0f + erff(u0 * 0.70710678118654752f));
                    Cp[1] = 0.5f * u1 * (1.0f + erff(u1 * 0.70710678118654752f));
                }
            }
        }
    }
}

// ----------------------------------------------------------------------------
// Fused flash attention. Block = (128 query rows) x (one b,h). 8 warps,
// each warp owns 16 query rows end-to-end. Bias computed on the fly.
// ----------------------------------------------------------------------------
__global__ void __launch_bounds__(256)
flash_attn(const float* __restrict__ xy, const int* __restrict__ alive,
           const int* __restrict__ species) {
    constexpr int QT = 128, JT = 64;
    constexpr int QST = 68, KST = 72, PST = 68, VST = 72;

    extern __shared__ float sm[];
    float* Qs  = sm;                   // 128*68
    float* Ps  = Qs  + QT * QST;       // 128*68
    float* Ks  = Ps  + QT * PST;       // 64*72  (transposed: [dh][j])
    float* Vs  = Ks  + JT * KST;       // 64*72  ([j][dh])
    float* kxs = Vs  + JT * VST;       // 64
    float* kys = kxs + JT;
    float* kng = kys + JT;
    float* kia = kng + JT;

    const int tid = threadIdx.x, lane = tid & 31, wid = tid >> 5;
    const int gid = lane >> 2, tig = lane & 3;
    const int m0 = blockIdx.x * QT;
    const int z = blockIdx.y, bb = z >> 3, hh = z & 7;

    const float* Qg = g_q + (size_t)bb * Nv * Dv + hh * DHv;
    const float* Kg = g_k + (size_t)bb * Nv * Dv + hh * DHv;
    const float* Vg = g_v + (size_t)bb * Nv * Dv + hh * DHv;
    float*       Og = g_o + (size_t)bb * Nv * Dv + hh * DHv;

    // async-load Q tile (128 x 64)
    #pragma unroll
    for (int s = 0; s < 8; s++) {
        int slot = tid + s * 256;
        int qr = slot >> 4, q4 = slot & 15;
        cp_async16(&Qs[qr * QST + q4 * 4], Qg + (size_t)(m0 + qr) * Dv + q4 * 4);
    }
    cp_commit();

    // per-thread query attrs (rows r0, r1 of this warp's 16-row tile)
    const int r0 = wid * 16 + gid, r1 = r0 + 8;
    const int gq0 = bb * Nv + m0 + r0, gq1 = bb * Nv + m0 + r1;
    const float qx0 = xy[gq0 * 2], qy0 = xy[gq0 * 2 + 1];
    const float qx1 = xy[gq1 * 2], qy1 = xy[gq1 * 2 + 1];
    const float qia0 = (species[gq0] < 2) ? 1.f : 0.f;
    const float qia1 = (species[gq1] < 2) ? 1.f : 0.f;

    float accO[8][4] = {};
    float mrow0 = -INFINITY, mrow1 = -INFINITY;
    float lrow0 = 0.f, lrow1 = 0.f;

    for (int j0 = 0; j0 < Nv; j0 += JT) {
        __syncthreads();   // previous chunk's PV done -> Ks/Vs reusable

        // K chunk: transpose into Ks (rna-rounded); V chunk: cp.async rows
        #pragma unroll
        for (int s = 0; s < 4; s++) {
            int slot = tid + s * 256;       // 1024 float4 slots
            int jl = slot >> 4, d4 = slot & 15;
            float4 kv = *(const float4*)(Kg + (size_t)(j0 + jl) * Dv + d4 * 4);
            Ks[(d4 * 4 + 0) * KST + jl] = to_tf32(kv.x);
            Ks[(d4 * 4 + 1) * KST + jl] = to_tf32(kv.y);
            Ks[(d4 * 4 + 2) * KST + jl] = to_tf32(kv.z);
            Ks[(d4 * 4 + 3) * KST + jl] = to_tf32(kv.w);
            cp_async16(&Vs[jl * VST + d4 * 4], Vg + (size_t)(j0 + jl) * Dv + d4 * 4);
        }
        cp_commit();
        if (tid < JT) {
            int gj = bb * Nv + j0 + tid;
            kxs[tid] = xy[gj * 2];
            kys[tid] = xy[gj * 2 + 1];
            kng[tid] = alive[gj] ? 0.f : NEGINF;
            kia[tid] = (species[gj] < 2) ? 1.f : 0.f;
        }
        cp_wait<0>();
        __syncthreads();

        // S = Q K^T  (warp rows wid*16..+16, cols 0..63)
        float accS[8][4] = {};
        mma_slab64<8>(Qs, QST, Ks, KST, accS, lane, wid * 16);

        // bias + chunk max
        float mc0 = -INFINITY, mc1 = -INFINITY;
        #pragma unroll
        for (int nt = 0; nt < 8; nt++) {
            #pragma unroll
            for (int c = 0; c < 2; c++) {
                int jl = nt * 8 + 2 * tig + c;
                float kx = kxs[jl], ky = kys[jl], kb = kng[jl], ki = kia[jl];
                float dx0 = qx0 - kx, dy0 = qy0 - ky;
                float b0 = kb;
                if (dx0 * dx0 + dy0 * dy0 > R2) b0 += NEGINF;
                if (qia0 != ki)                 b0 += NEGINF;
                float s0 = accS[nt][c] * 0.125f + b0;
                accS[nt][c] = s0; mc0 = fmaxf(mc0, s0);

                float dx1 = qx1 - kx, dy1 = qy1 - ky;
                float b1 = kb;
                if (dx1 * dx1 + dy1 * dy1 > R2) b1 += NEGINF;
                if (qia1 != ki)                 b1 += NEGINF;
                float s1 = accS[nt][c + 2] * 0.125f + b1;
                accS[nt][c + 2] = s1; mc1 = fmaxf(mc1, s1);
            }
        }
        mc0 = fmaxf(mc0, __shfl_xor_sync(0xffffffffu, mc0, 1));
        mc0 = fmaxf(mc0, __shfl_xor_sync(0xffffffffu, mc0, 2));
        mc1 = fmaxf(mc1, __shfl_xor_sync(0xffffffffu, mc1, 1));
        mc1 = fmaxf(mc1, __shfl_xor_sync(0xffffffffu, mc1, 2));

        float mn0 = fmaxf(mrow0, mc0), mn1 = fmaxf(mrow1, mc1);
        float sc0 = __expf(mrow0 - mn0), sc1 = __expf(mrow1 - mn1);

        float sum0 = 0.f, sum1 = 0.f;
        #pragma unroll
        for (int nt = 0; nt < 8; nt++) {
            #pragma unroll
            for (int c = 0; c < 2; c++) {
                int jl = nt * 8 + 2 * tig + c;
                float p0 = __expf(accS[nt][c]     - mn0);
                float p1 = __expf(accS[nt][c + 2] - mn1);
                sum0 += p0; sum1 += p1;
                Ps[r0 * PST + jl] = p0;
                Ps[r1 * PST + jl] = p1;
            }
        }
        sum0 += __shfl_xor_sync(0xffffffffu, sum0, 1);
        sum0 += __shfl_xor_sync(0xffffffffu, sum0, 2);
        sum1 += __shfl_xor_sync(0xffffffffu, sum1, 1);
        sum1 += __shfl_xor_sync(0xffffffffu, sum1, 2);

        lrow0 = lrow0 * sc0 + sum0;
        lrow1 = lrow1 * sc1 + sum1;
        mrow0 = mn0; mrow1 = mn1;

        #pragma unroll
        for (int nt = 0; nt < 8; nt++) {
            accO[nt][0] *= sc0; accO[nt][1] *= sc0;
            accO[nt][2] *= sc1; accO[nt][3] *= sc1;
        }

        __syncwarp();   // P rows are warp-private; warp-level visibility suffices
        mma_slab64<8>(Ps, PST, Vs, VST, accO, lane, wid * 16);
    }

    // epilogue: normalize and store
    float il0 = 1.f / lrow0, il1 = 1.f / lrow1;
    #pragma unroll
    for (int nt = 0; nt < 8; nt++) {
        int col = nt * 8 + 2 * tig;
        float* o0 = Og + (size_t)(m0 + r0) * Dv + col;
        float* o1 = Og + (size_t)(m0 + r1) * Dv + col;
        o0[0] = accO[nt][0] * il0; o0[1] = accO[nt][1] * il0;
        o1[0] = accO[nt][2] * il1; o1[1] = accO[nt][3] * il1;
    }
}

// ============================================================================
// Launch sequence
// ============================================================================
extern "C" void kernel_launch(void* const* d_in, const int* in_sizes, int n_in,
                              void* d_out, int out_size) {
    const float* tokens = (const float*)d_in[0];
    const float* xy     = (const float*)d_in[1];
    const float* Wq     = (const float*)d_in[2];
    const float* Wk     = (const float*)d_in[3];
    const float* Wv     = (const float*)d_in[4];
    const float* Wo     = (const float*)d_in[5];
    const float* bo     = (const float*)d_in[6];
    const float* W1     = (const float*)d_in[7];
    const float* b1     = (const float*)d_in[8];
    const float* W2     = (const float*)d_in[9];
    const float* b2     = (const float*)d_in[10];
    const float* g1     = (const float*)d_in[11];
    const float* be1    = (const float*)d_in[12];
    const float* g2     = (const float*)d_in[13];
    const float* be2    = (const float*)d_in[14];
    const float* gf     = (const float*)d_in[15];
    const float* bf     = (const float*)d_in[16];
    const int*   alive  = (const int*)d_in[17];
    const int*   species= (const int*)d_in[18];
    float* out = (float*)d_out;

    constexpr int FLASH_SMEM = (128 * 68 * 2 + 64 * 72 * 2 + 4 * 64) * 4;  // 107520
    cudaFuncSetAttribute(flash_attn, cudaFuncAttributeMaxDynamicSharedMemorySize,
                         FLASH_SMEM);

    copy_tokens<<<(ROWS * Dv / 4) / 256, 256>>>((const float4*)tokens);

    for (int l = 0; l < Lv; l++) {
        // ln1: x -> h
        ln_kernel<<<ROWS, 128>>>(6, 0, nullptr, g1 + l * Dv, be1 + l * Dv);
        // fused Q/K/V projections (z selects weight & output)
        gemm2<0><<<dim3(Dv / 128, ROWS / 128, 3), 256>>>(
            0, Wq + (size_t)l * Dv * Dv, Wk + (size_t)l * Dv * Dv,
            Wv + (size_t)l * Dv * Dv, 3, ROWS, Dv, Dv, nullptr);
        // fused attention -> g_o
        flash_attn<<<dim3(Nv / 128, Bv * 8), 256, FLASH_SMEM>>>(xy, alive, species);
        // x += O Wo + bo
        gemm2<1><<<dim3(Dv / 128, ROWS / 128, 1), 256>>>(
            1, Wo + (size_t)l * Dv * Dv, nullptr, nullptr, 6, ROWS, Dv, Dv, bo + l * Dv);
        // ln2: x -> h
        ln_kernel<<<ROWS, 128>>>(6, 0, nullptr, g2 + l * Dv, be2 + l * Dv);
        // ff = gelu(h W1 + b1)
        gemm2<2><<<dim3(DFFv / 128, ROWS / 128, 1), 256>>>(
            0, W1 + (size_t)l * Dv * DFFv, nullptr, nullptr, 2, ROWS, DFFv, Dv, b1 + l * DFFv);
        // x += ff W2 + b2
        gemm2<1><<<dim3(Dv / 128, ROWS / 128, 1), 256>>>(
            2, W2 + (size_t)l * DFFv * Dv, nullptr, nullptr, 6, ROWS, Dv, DFFv, b2 + l * Dv);
    }

    // final layernorm -> out
    ln_kernel<<<ROWS, 128>>>(6, 1, out, gf, bf);
}